// round 8
// baseline (speedup 1.0000x reference)
#include <cuda_runtime.h>
#include <cstdint>

// DiceFromLabelsLoss — single fused kernel, round 8 (R7 + missing include fix).
// Per (batch, class c in 1..9): P=#(yp==c), T=#(yt==c), I=#(yp==c && yt==c).
// loss = 1 - sum_n sum_c [P+T>0] * (T / sumT / NB) * (2I/(P+T))
//
// Hot loop: cp.async.cg 4-stage smem ring (prefetch distance 3) -> deep,
// register-independent MLP. Each thread reads back only its own slot, so the
// pipeline needs no block-level syncs. 64-bit packed histogram accumulators
// (10 classes x 6-bit fields), flushed every <=9 iterations into 16-bit
// packed per-class register totals.

#define NB 4
#define NC 9
#define BX 74
#define TPB 512
#define STRIDE (BX * TPB)  // 37888 int4 per grid-stride step
#define STAGES 4

__device__ unsigned g_hist[NB][3][NC];  // [batch][{P,T,I}][class-1]
__device__ unsigned g_done;

__device__ __forceinline__ void cp16(unsigned int dst_smem, const void* src) {
    asm volatile("cp.async.cg.shared.global [%0], [%1], 16;"
                 :: "r"(dst_smem), "l"(src) : "memory");
}
__device__ __forceinline__ void cp_commit() {
    asm volatile("cp.async.commit_group;" ::: "memory");
}
__device__ __forceinline__ void cp_wait2() {
    asm volatile("cp.async.wait_group 2;" ::: "memory");
}

__device__ __forceinline__ void proc(const int4 a, const int4 b,
                                     unsigned long long& aP,
                                     unsigned long long& aT,
                                     unsigned long long& aI) {
    const int va[4] = {a.x, a.y, a.z, a.w};
    const int vb[4] = {b.x, b.y, b.z, b.w};
#pragma unroll
    for (int j = 0; j < 4; j++) {
        const unsigned long long pa = 1ull << (6 * va[j]);
        aP += pa;
        aT += 1ull << (6 * vb[j]);
        if (va[j] == vb[j]) aI += pa;
    }
}

__global__ __launch_bounds__(TPB, 2) void dice_fused_kernel(
    const int4* __restrict__ yp, const int4* __restrict__ yt,
    int n4_per_batch, int nblocks_total, float* __restrict__ out) {
    const int n = blockIdx.y;
    const int tid = threadIdx.x;
    const int base = blockIdx.x * TPB + tid;

    // Smem ring: [STAGES][TPB] for yp then [STAGES][TPB] for yt.
    extern __shared__ int4 sbuf[];
    const int4* __restrict__ bP = sbuf;
    const int4* __restrict__ bT = sbuf + STAGES * TPB;
    const unsigned int sb = (unsigned int)__cvta_generic_to_shared(sbuf);
    const unsigned int dP0 = sb + (unsigned int)tid * 16u;
    const unsigned int dT0 = sb + (unsigned int)(STAGES * TPB + tid) * 16u;

    __shared__ unsigned sh[3 * NC];
    __shared__ unsigned s_last;
    if (tid < 3 * NC) sh[tid] = 0u;
    __syncthreads();

    const int4* __restrict__ gp = yp + (size_t)n * n4_per_batch + base;
    const int4* __restrict__ gt = yt + (size_t)n * n4_per_batch + base;
    const int nfull = n4_per_batch / STRIDE;  // uniform across all threads

    // 16-bit packed per-class totals: class c -> pk[(c-1)>>1], half (c-1)&1.
    // Per-thread per-class max ~= 4*(nfull+1) ~= 112 << 65535.
    unsigned pkP[5], pkT[5], pkI[5];
#pragma unroll
    for (int r = 0; r < 5; r++) { pkP[r] = 0u; pkT[r] = 0u; pkI[r] = 0u; }

#define FLUSH(aP, aT, aI)                                                  \
    {                                                                      \
        _Pragma("unroll") for (int c = 1; c <= NC; c++) {                  \
            const int r = (c - 1) >> 1;                                    \
            const int shl = ((c - 1) & 1) * 16;                            \
            pkP[r] += (((unsigned)((aP) >> (6 * c))) & 63u) << shl;        \
            pkT[r] += (((unsigned)((aT) >> (6 * c))) & 63u) << shl;        \
            pkI[r] += (((unsigned)((aI) >> (6 * c))) & 63u) << shl;        \
        }                                                                  \
    }

    // Prologue: prefetch stages 0..STAGES-2 (one commit group per stage).
#pragma unroll
    for (int s = 0; s < STAGES - 1; s++) {
        if (s < nfull) {
            cp16(dP0 + (unsigned int)(s * TPB) * 16u, gp + (size_t)s * STRIDE);
            cp16(dT0 + (unsigned int)(s * TPB) * 16u, gt + (size_t)s * STRIDE);
        }
        cp_commit();
    }
    const int4* pfP = gp + (size_t)(STAGES - 1) * STRIDE;
    const int4* pfT = gt + (size_t)(STAGES - 1) * STRIDE;

    int k = 0;
    while (k < nfull) {
        const int wend = (k + 9 <= nfull) ? k + 9 : nfull;
        unsigned long long aP = 0ull, aT = 0ull, aI = 0ull;
        for (; k < wend; k++) {
            cp_wait2();  // stage k resident
            const int s = k & (STAGES - 1);
            const int4 a = bP[s * TPB + tid];
            const int4 b = bT[s * TPB + tid];
            // Prefetch stage k+STAGES-1 (uniform predicate; always commit).
            if (k + STAGES - 1 < nfull) {
                cp16(dP0 + (unsigned int)(s * TPB) * 16u, pfP);
                cp16(dT0 + (unsigned int)(s * TPB) * 16u, pfT);
            }
            pfP += STRIDE;
            pfT += STRIDE;
            cp_commit();
            proc(a, b, aP, aT, aI);
        }
        FLUSH(aP, aT, aI)  // <= 36 increments, capacity 63
    }
    {   // Ragged remainder (<=1 int4 per thread), plain guarded load.
        if (base + nfull * STRIDE < n4_per_batch) {
            unsigned long long aP = 0ull, aT = 0ull, aI = 0ull;
            proc(gp[(size_t)nfull * STRIDE], gt[(size_t)nfull * STRIDE], aP, aT, aI);
            FLUSH(aP, aT, aI)
        }
    }
#undef FLUSH

    // Unpack, warp butterfly reduce, one smem atomic per warp per counter.
    unsigned P[NC], T[NC], I[NC];
#pragma unroll
    for (int c = 0; c < NC; c++) {
        const int r = c >> 1;
        const int shl = (c & 1) * 16;
        P[c] = (pkP[r] >> shl) & 0xFFFFu;
        T[c] = (pkT[r] >> shl) & 0xFFFFu;
        I[c] = (pkI[r] >> shl) & 0xFFFFu;
    }
#pragma unroll
    for (int c = 0; c < NC; c++) {
#pragma unroll
        for (int off = 16; off; off >>= 1) {
            P[c] += __shfl_xor_sync(0xFFFFFFFFu, P[c], off);
            T[c] += __shfl_xor_sync(0xFFFFFFFFu, T[c], off);
            I[c] += __shfl_xor_sync(0xFFFFFFFFu, I[c], off);
        }
    }
    if ((tid & 31) == 0) {
#pragma unroll
        for (int c = 0; c < NC; c++) {
            atomicAdd(&sh[c], P[c]);
            atomicAdd(&sh[NC + c], T[c]);
            atomicAdd(&sh[2 * NC + c], I[c]);
        }
    }
    __syncthreads();
    if (tid < 3 * NC)
        atomicAdd(&(&g_hist[n][0][0])[tid], sh[tid]);

    // Last-block-done finalize + self-rezero (graph-replay safe).
    __threadfence();
    if (tid == 0) {
        unsigned ticket = atomicAdd(&g_done, 1u);
        s_last = (ticket == (unsigned)(nblocks_total - 1)) ? 1u : 0u;
    }
    __syncthreads();
    if (s_last) {
        if (tid == 0) {
            __threadfence();
            float acc = 0.0f;
#pragma unroll
            for (int b = 0; b < NB; b++) {
                float sumT = 0.0f;
#pragma unroll
                for (int c = 0; c < NC; c++) sumT += (float)g_hist[b][1][c];
                const float winv = (sumT > 0.0f) ? 1.0f / (sumT * (float)NB) : 0.0f;
#pragma unroll
                for (int c = 0; c < NC; c++) {
                    const float Pp = (float)g_hist[b][0][c];
                    const float Tt = (float)g_hist[b][1][c];
                    const float Ii = (float)g_hist[b][2][c];
                    const float d = Pp + Tt;
                    if (d > 0.0f) acc += (Tt * winv) * (2.0f * Ii / d);
                }
            }
            out[0] = 1.0f - acc;
        }
        __syncthreads();  // finalize read complete before re-zeroing
        if (tid < NB * 3 * NC) (&g_hist[0][0][0])[tid] = 0u;
        if (tid == 0) g_done = 0u;
    }
}

extern "C" void kernel_launch(void* const* d_in, const int* in_sizes, int n_in,
                              void* d_out, int out_size) {
    const int4* yp = (const int4*)d_in[0];
    const int4* yt = (const int4*)d_in[1];
    const int total = in_sizes[0];     // 16,384,000
    const int per_batch = total / NB;  // 4,096,000
    const int n4 = per_batch / 4;      // 1,024,000 int4 per batch

    const int smem_bytes = STAGES * 2 * TPB * 16;  // 64 KB ring
    static bool attr_set = false;
    if (!attr_set) {
        cudaFuncSetAttribute(dice_fused_kernel,
                             cudaFuncAttributeMaxDynamicSharedMemorySize,
                             smem_bytes);
        attr_set = true;
    }
    dim3 grid(BX, NB);  // 296 CTAs x 512 threads = 2 CTAs/SM (smem: 128 KB/SM)
    dice_fused_kernel<<<grid, TPB, smem_bytes>>>(yp, yt, n4, BX * NB,
                                                 (float*)d_out);
}